// round 6
// baseline (speedup 1.0000x reference)
#include <cuda_runtime.h>
#include <cuda_fp16.h>
#include <cstdint>

// ---------------- problem constants ----------------
#define NCOLS 8192
#define BLK   256
#define NBLK  16

// ---------------- tile config ----------------
#define BN 128      // output cols per CTA
#define KC 16       // K chunk
#define NCHUNK 16   // 256/16

// ---------------- SMEM layout ----------------
// A: whole W block as fp16: 256 rows x (256 fp16 = 512B + 16B pad) = 528B/row
// B: two stages, 16 rows x (128 fp16 = 256B + 16B pad) = 272B/row
#define A_ROW 528
#define B_ROW 272
#define OFF_B (256 * A_ROW)              // 135168
#define B_STAGE (KC * B_ROW)             // 4352
#define SMEM_TOTAL (OFF_B + 2 * B_STAGE) // 143872

// ---------------- helpers ----------------
__device__ __forceinline__ uint32_t smem_u32(const void* p) {
    uint32_t a;
    asm("{ .reg .u64 t; cvta.to.shared.u64 t, %1; cvt.u32.u64 %0, t; }" : "=r"(a) : "l"(p));
    return a;
}

// pack two fp32 -> fp16x2 (x0 in low half)
__device__ __forceinline__ uint32_t cvt_f16x2(float x0, float x1) {
    uint32_t r;
    asm("cvt.rn.f16x2.f32 %0, %1, %2;" : "=r"(r) : "f"(x1), "f"(x0));
    return r;
}

__device__ __forceinline__ void ldm_x4(uint32_t (&r)[4], uint32_t addr) {
    asm volatile("ldmatrix.sync.aligned.m8n8.x4.shared.b16 {%0,%1,%2,%3}, [%4];"
                 : "=r"(r[0]), "=r"(r[1]), "=r"(r[2]), "=r"(r[3]) : "r"(addr));
}

__device__ __forceinline__ void ldm_x2t(uint32_t (&r)[2], uint32_t addr) {
    asm volatile("ldmatrix.sync.aligned.m8n8.x2.trans.shared.b16 {%0,%1}, [%2];"
                 : "=r"(r[0]), "=r"(r[1]) : "r"(addr));
}

__device__ __forceinline__ void mma_f16(float (&d)[4], const uint32_t (&a)[4],
                                        const uint32_t (&b)[2]) {
    asm volatile(
        "mma.sync.aligned.m16n8k16.row.col.f32.f16.f16.f32 "
        "{%0,%1,%2,%3}, {%4,%5,%6,%7}, {%8,%9}, {%0,%1,%2,%3};"
        : "+f"(d[0]), "+f"(d[1]), "+f"(d[2]), "+f"(d[3])
        : "r"(a[0]), "r"(a[1]), "r"(a[2]), "r"(a[3]), "r"(b[0]), "r"(b[1]));
}

// ---------------- kernel ----------------
__global__ void __launch_bounds__(256, 1)
blk_gemm(const float* __restrict__ X,   // [4096, 8192]
         const float* __restrict__ W,   // [16, 256, 256]
         float* __restrict__ out)       // [4096, 8192]
{
    extern __shared__ char smem[];
    const uint32_t sb = smem_u32(smem);
    const int tid  = threadIdx.x;
    const int lane = tid & 31;
    const int w    = tid >> 5;     // 0..7
    const int wm   = w & 3;        // M quadrant (64 rows)
    const int wn   = w >> 2;       // N half (64 cols of 128)
    const int b    = blockIdx.x >> 6;
    const int nt   = blockIdx.x & 63;

    const float* Xb = X + (size_t)b * BLK * NCOLS + (size_t)nt * BN;
    const float* Wb = W + (size_t)b * (BLK * BLK);

    // acc: 4 M-subtiles x 8 N-subtiles (warp tile 64 x 64)
    float acc[4][8][4];
    #pragma unroll
    for (int mi = 0; mi < 4; mi++)
        #pragma unroll
        for (int nj = 0; nj < 8; nj++)
            #pragma unroll
            for (int q = 0; q < 4; q++) acc[mi][nj][q] = 0.f;

    // ---- prologue: convert ENTIRE W block to fp16 in SMEM (once) ----
    {
        const float2* Wb2 = (const float2*)Wb;   // 32768 float2
        #pragma unroll 8
        for (int i = 0; i < 128; i++) {
            const int idx  = tid + 256 * i;
            const int row  = idx >> 7;        // 128 float2 per row
            const int col2 = idx & 127;
            float2 v = Wb2[idx];
            *(uint32_t*)(smem + row * A_ROW + col2 * 4) = cvt_f16x2(v.x, v.y);
        }
    }

    // ---- B pipeline prologue ----
    // per chunk: 16 rows x 128 cols fp32 = 512 float4; 256 threads -> 2 each
    const int br = tid >> 5;          // base row 0..7 (+8*i)
    const int bc = tid & 31;          // float4 col 0..31
    float4 bR[2];
    // chunk 0 -> regs -> stage 0
    #pragma unroll
    for (int i = 0; i < 2; i++)
        bR[i] = *(const float4*)(Xb + (size_t)(br + 8 * i) * NCOLS + 4 * bc);
    #pragma unroll
    for (int i = 0; i < 2; i++) {
        uint2 hv;
        hv.x = cvt_f16x2(bR[i].x, bR[i].y);
        hv.y = cvt_f16x2(bR[i].z, bR[i].w);
        *(uint2*)(smem + OFF_B + (br + 8 * i) * B_ROW + bc * 8) = hv;
    }
    // prefetch chunk 1 -> regs
    #pragma unroll
    for (int i = 0; i < 2; i++)
        bR[i] = *(const float4*)(Xb + (size_t)(KC + br + 8 * i) * NCOLS + 4 * bc);
    __syncthreads();

    // ---- main loop: one barrier per chunk; STS/LDG overlapped with MMA ----
    #pragma unroll 4
    for (int c = 0; c < NCHUNK; c++) {
        const uint32_t sBr = sb + OFF_B + (c & 1) * B_STAGE;          // read stage
        char* const    pBw = smem + OFF_B + ((c + 1) & 1) * B_STAGE;  // write stage

        // A fragments: rows wm*64 + mi*16 + (lane&15), k bytes c*32 + (lane>>4)*16
        const uint32_t a_off =
            (uint32_t)((wm * 64 + (lane & 15)) * A_ROW + c * 32 + (lane >> 4) * 16);
        // B fragments: k rows (lane&15), n byte base wn*128 (64 fp16)
        const uint32_t b_off =
            (uint32_t)((lane & 15) * B_ROW + wn * 128);

        uint32_t Ah[4][4], Bh[8][2];
        #pragma unroll
        for (int mi = 0; mi < 4; mi++)
            ldm_x4(Ah[mi], sb + a_off + mi * 16 * A_ROW);
        #pragma unroll
        for (int nj = 0; nj < 8; nj++)
            ldm_x2t(Bh[nj], sBr + b_off + nj * 16);

        // overlapped B pipeline work (independent of MMAs below)
        if (c < NCHUNK - 1) {
            #pragma unroll
            for (int i = 0; i < 2; i++) {
                uint2 hv;
                hv.x = cvt_f16x2(bR[i].x, bR[i].y);
                hv.y = cvt_f16x2(bR[i].z, bR[i].w);
                *(uint2*)(pBw + (br + 8 * i) * B_ROW + bc * 8) = hv;
            }
        }
        if (c < NCHUNK - 2) {
            #pragma unroll
            for (int i = 0; i < 2; i++)
                bR[i] = *(const float4*)(Xb + (size_t)((c + 2) * KC + br + 8 * i) * NCOLS +
                                         4 * bc);
        }

        #pragma unroll
        for (int mi = 0; mi < 4; mi++)
            #pragma unroll
            for (int nj = 0; nj < 8; nj++)
                mma_f16(acc[mi][nj], Ah[mi], Bh[nj]);

        __syncthreads();
    }

    // ---- epilogue: registers -> global ----
    const int r0 = b * BLK + wm * 64 + (lane >> 2);
    const int c0 = nt * BN + wn * 64 + (lane & 3) * 2;
    #pragma unroll
    for (int mi = 0; mi < 4; mi++)
        #pragma unroll
        for (int nj = 0; nj < 8; nj++) {
            float2 v0; v0.x = acc[mi][nj][0]; v0.y = acc[mi][nj][1];
            float2 v1; v1.x = acc[mi][nj][2]; v1.y = acc[mi][nj][3];
            const size_t base = (size_t)(r0 + mi * 16) * NCOLS + (size_t)(c0 + nj * 8);
            *(float2*)(out + base) = v0;
            *(float2*)(out + base + (size_t)8 * NCOLS) = v1;
        }
}

// ---------------- launch ----------------
extern "C" void kernel_launch(void* const* d_in, const int* in_sizes, int n_in,
                              void* d_out, int out_size) {
    const float* X = (const float*)d_in[0];   // inp [4096, 8192]
    const float* W = (const float*)d_in[1];   // W   [16, 256, 256]
    float* out = (float*)d_out;

    cudaFuncSetAttribute(blk_gemm, cudaFuncAttributeMaxDynamicSharedMemorySize, SMEM_TOTAL);

    dim3 grid(NBLK * (NCOLS / BN));   // 16 * 64 = 1024
    blk_gemm<<<grid, 256, SMEM_TOTAL>>>(X, W, out);
}

// round 7
// speedup vs baseline: 1.1640x; 1.1640x over previous
#include <cuda_runtime.h>
#include <cuda_fp16.h>
#include <cstdint>

// ---------------- problem constants ----------------
#define NCOLS 8192
#define BLK   256
#define NBLK  16

// ---------------- tile config ----------------
#define BN 128      // output cols per CTA
#define KC 16       // K chunk
#define NCHUNK 16   // 256/16

// ---------------- SMEM layout (A only) ----------------
// A: whole W block fp16: 256 rows x (256 fp16 = 512B + 16B pad) = 528B/row
#define A_ROW 528
#define SMEM_TOTAL (256 * A_ROW)   // 135168

// fp16 copy of W, produced once per launch by conv_w kernel (2 MB)
__device__ __half g_Wh[NBLK * BLK * BLK];

// ---------------- helpers ----------------
__device__ __forceinline__ uint32_t smem_u32(const void* p) {
    uint32_t a;
    asm("{ .reg .u64 t; cvta.to.shared.u64 t, %1; cvt.u32.u64 %0, t; }" : "=r"(a) : "l"(p));
    return a;
}

// pack two fp32 -> fp16x2 (x0 in low half)
__device__ __forceinline__ uint32_t cvt_f16x2(float x0, float x1) {
    uint32_t r;
    asm("cvt.rn.f16x2.f32 %0, %1, %2;" : "=r"(r) : "f"(x1), "f"(x0));
    return r;
}

__device__ __forceinline__ void ldm_x4(uint32_t (&r)[4], uint32_t addr) {
    asm volatile("ldmatrix.sync.aligned.m8n8.x4.shared.b16 {%0,%1,%2,%3}, [%4];"
                 : "=r"(r[0]), "=r"(r[1]), "=r"(r[2]), "=r"(r[3]) : "r"(addr));
}

__device__ __forceinline__ void mma_f16(float (&d)[4], const uint32_t (&a)[4],
                                        const uint32_t b0, const uint32_t b1) {
    asm volatile(
        "mma.sync.aligned.m16n8k16.row.col.f32.f16.f16.f32 "
        "{%0,%1,%2,%3}, {%4,%5,%6,%7}, {%8,%9}, {%0,%1,%2,%3};"
        : "+f"(d[0]), "+f"(d[1]), "+f"(d[2]), "+f"(d[3])
        : "r"(a[0]), "r"(a[1]), "r"(a[2]), "r"(a[3]), "r"(b0), "r"(b1));
}

// ---------------- W fp32 -> fp16 pre-pass ----------------
__global__ void conv_w(const float* __restrict__ W) {
    const int i = blockIdx.x * blockDim.x + threadIdx.x;   // over float2 pairs
    const float2 v = ((const float2*)W)[i];
    *(uint32_t*)&g_Wh[2 * i] = cvt_f16x2(v.x, v.y);
}

// ---------------- main kernel ----------------
__global__ void __launch_bounds__(256, 1)
blk_gemm(const float* __restrict__ X,   // [4096, 8192]
         float* __restrict__ out)       // [4096, 8192]
{
    extern __shared__ char smem[];
    const uint32_t sb = smem_u32(smem);
    const int tid  = threadIdx.x;
    const int lane = tid & 31;
    const int w    = tid >> 5;     // 0..7
    const int wm   = w & 1;        // M half (128 rows)
    const int wn   = w >> 1;       // N quarter (32 cols)
    const int b    = blockIdx.x >> 6;
    const int nt   = blockIdx.x & 63;

    // B fragment element coordinates for this lane
    const int k0 = (lane & 3) * 2;        // 0,2,4,6
    const int nl = (lane >> 2);           // 0..7 within 8-col fragment

    // per-thread X base: row k0, col (nt*128 + wn*32 + nl)
    const float* Xp = X + (size_t)(b * BLK + k0) * NCOLS + nt * BN + wn * 32 + nl;

    // ---- issue B chunk 0 loads FIRST (DRAM latency overlapped with W copy) ----
    float braw[4][4];   // [nj][j], j: k0, k0+1, k0+8, k0+9
    #pragma unroll
    for (int nj = 0; nj < 4; nj++) {
        const float* p = Xp + nj * 8;
        braw[nj][0] = p[0];
        braw[nj][1] = p[NCOLS];
        braw[nj][2] = p[(size_t)8 * NCOLS];
        braw[nj][3] = p[(size_t)9 * NCOLS];
    }

    // ---- prologue: copy W block (fp16, pre-converted) into SMEM ----
    {
        const uint4* src = (const uint4*)(g_Wh + (size_t)b * (BLK * BLK));  // 8192 uint4
        #pragma unroll 8
        for (int i = 0; i < 32; i++) {
            const int idx = tid + 256 * i;
            const int row = idx >> 5;         // 32 uint4 per row
            const int c16 = idx & 31;
            *(uint4*)(smem + row * A_ROW + c16 * 16) = src[idx];
        }
    }

    float acc[8][4][4];
    #pragma unroll
    for (int mi = 0; mi < 8; mi++)
        #pragma unroll
        for (int nj = 0; nj < 4; nj++)
            #pragma unroll
            for (int q = 0; q < 4; q++) acc[mi][nj][q] = 0.f;

    __syncthreads();   // the ONLY barrier: W tile ready

    // ---- main loop: no barriers; B prefetched one chunk ahead ----
    float brnx[4][4];
    #pragma unroll 2
    for (int c = 0; c < NCHUNK; c++) {
        // prefetch B for chunk c+1
        if (c < NCHUNK - 1) {
            const float* pc = Xp + (size_t)(c + 1) * KC * NCOLS;
            #pragma unroll
            for (int nj = 0; nj < 4; nj++) {
                const float* p = pc + nj * 8;
                brnx[nj][0] = p[0];
                brnx[nj][1] = p[NCOLS];
                brnx[nj][2] = p[(size_t)8 * NCOLS];
                brnx[nj][3] = p[(size_t)9 * NCOLS];
            }
        }

        // A fragments from SMEM: rows wm*128 + mi*16 + (lane&15), k bytes c*32
        const uint32_t a_off =
            (uint32_t)((wm * 128 + (lane & 15)) * A_ROW + c * 32 + (lane >> 4) * 16);
        uint32_t Ah[8][4];
        #pragma unroll
        for (int mi = 0; mi < 8; mi++)
            ldm_x4(Ah[mi], sb + a_off + mi * 16 * A_ROW);

        // convert current B raw -> fragments
        uint32_t b0[4], b1[4];
        #pragma unroll
        for (int nj = 0; nj < 4; nj++) {
            b0[nj] = cvt_f16x2(braw[nj][0], braw[nj][1]);
            b1[nj] = cvt_f16x2(braw[nj][2], braw[nj][3]);
        }

        #pragma unroll
        for (int mi = 0; mi < 8; mi++)
            #pragma unroll
            for (int nj = 0; nj < 4; nj++)
                mma_f16(acc[mi][nj], Ah[mi], b0[nj], b1[nj]);

        // rotate prefetch buffer
        #pragma unroll
        for (int nj = 0; nj < 4; nj++)
            #pragma unroll
            for (int j = 0; j < 4; j++) braw[nj][j] = brnx[nj][j];
    }

    // ---- epilogue: registers -> global ----
    const int r0 = b * BLK + wm * 128 + (lane >> 2);
    const int c0 = nt * BN + wn * 32 + (lane & 3) * 2;
    #pragma unroll
    for (int mi = 0; mi < 8; mi++)
        #pragma unroll
        for (int nj = 0; nj < 4; nj++) {
            float2 v0; v0.x = acc[mi][nj][0]; v0.y = acc[mi][nj][1];
            float2 v1; v1.x = acc[mi][nj][2]; v1.y = acc[mi][nj][3];
            const size_t base = (size_t)(r0 + mi * 16) * NCOLS + (size_t)(c0 + nj * 8);
            *(float2*)(out + base) = v0;
            *(float2*)(out + base + (size_t)8 * NCOLS) = v1;
        }
}

// ---------------- launch ----------------
extern "C" void kernel_launch(void* const* d_in, const int* in_sizes, int n_in,
                              void* d_out, int out_size) {
    const float* X = (const float*)d_in[0];   // inp [4096, 8192]
    const float* W = (const float*)d_in[1];   // W   [16, 256, 256]
    float* out = (float*)d_out;

    // pass 1: W -> fp16 (1M float2 pairs / 256 = 2048 blocks)
    conv_w<<<(NBLK * BLK * BLK / 2) / 256, 256>>>(W);

    cudaFuncSetAttribute(blk_gemm, cudaFuncAttributeMaxDynamicSharedMemorySize, SMEM_TOTAL);
    dim3 grid(NBLK * (NCOLS / BN));   // 16 * 64 = 1024
    blk_gemm<<<grid, 256, SMEM_TOTAL>>>(X, out);
}